// round 12
// baseline (speedup 1.0000x reference)
#include <cuda_runtime.h>
#include <cuda_bf16.h>
#include <cuda_fp16.h>
#include <mma.h>
#include <math.h>
#include <stdint.h>

using namespace nvcuda;

#define NN 50000
#define EE 800000
#define KDIM 128
#define CD 128
#define NH 8

#define BM 64        // edges per tile
#define NTILE (EE / BM)   // 12500
#define AW 136       // A smem leading dim, full-K fp16
#define AFULL 136    // node A leading dim (bf16)
#define BLD 136      // B smem leading dim
#define PLD 132      // proj staging leading dim (floats), 32 rows per pass

// ---------------- device scratch ----------------
__device__ float g_Qh[(size_t)NN * CD];
__device__ float g_Kh[(size_t)NN * CD];
__device__ float g_Vh[(size_t)NN * CD];
__device__ float g_z[(size_t)NN * NH];
__device__ unsigned int g_blk;
// edge weights: single fp16 (0=Ew 1=Rw)
__device__ __align__(16) __half g_We[2][KDIM * CD];
// node weights: bf16 hi/lo (0=Qw 1=Kw 2=Vw)
__device__ __align__(16) __nv_bfloat16 g_Wn_h[3][KDIM * CD];
__device__ __align__(16) __nv_bfloat16 g_Wn_l[3][KDIM * CD];

__device__ __forceinline__ void red_add_v4(float* p, float a, float b, float c, float d) {
    asm volatile("red.global.add.v4.f32 [%0], {%1, %2, %3, %4};"
                 :: "l"(p), "f"(a), "f"(b), "f"(c), "f"(d) : "memory");
}
__device__ __forceinline__ void cvt_split_bf(float x, __nv_bfloat16& hi, __nv_bfloat16& lo) {
    hi = __float2bfloat16(x);
    lo = __float2bfloat16(x - __bfloat162float(hi));
}
__device__ __forceinline__ void cp16(uint32_t saddr, const void* gptr) {
    asm volatile("cp.async.cg.shared.global [%0], [%1], 16;"
                 :: "r"(saddr), "l"(gptr) : "memory");
}
__device__ __forceinline__ void cp_commit() {
    asm volatile("cp.async.commit_group;" ::: "memory");
}
__device__ __forceinline__ void cp_wait_all() {
    asm volatile("cp.async.wait_group 0;" ::: "memory");
}

// ---------------- weight conversion (once per launch) ----------------
__global__ __launch_bounds__(256) void convert_weights_kernel(
    const float* __restrict__ Ew, const float* __restrict__ Rw,
    const float* __restrict__ Qw, const float* __restrict__ Kw,
    const float* __restrict__ Vw)
{
    int i = blockIdx.x * 256 + threadIdx.x;
    if (i >= KDIM * CD) return;
    g_We[0][i] = __float2half_rn(Ew[i]);
    g_We[1][i] = __float2half_rn(Rw[i]);
    {
        __nv_bfloat16 h, l;
        cvt_split_bf(Qw[i], h, l); g_Wn_h[0][i] = h; g_Wn_l[0][i] = l;
        cvt_split_bf(Kw[i], h, l); g_Wn_h[1][i] = h; g_Wn_l[1][i] = l;
        cvt_split_bf(Vw[i], h, l); g_Wn_h[2][i] = h; g_Wn_l[2][i] = l;
    }
}

// ================= persistent edge kernel =================
// smem: sidx 512 | BE 34816 | BR 34816 | A (AE+AK full-K) 34816
// proj staging (two passes of 32 edges, R+E) aliases the dead A region.
#define ESM_SIDX  0
#define ESM_BE    512
#define ESM_BR    (ESM_BE + KDIM * BLD * 2)
#define ESM_A     (ESM_BR + KDIM * BLD * 2)
#define ESM_TOTAL (ESM_A + 2 * BM * AW * 2)   // 104960
#define PROJ_HALF (32 * PLD * 4)              // 16896

__global__ __launch_bounds__(256, 2) void edge_kernel(
    const float* __restrict__ e,
    const float* __restrict__ kr,
    const int*  __restrict__ src,
    const int*  __restrict__ dst,
    const float* __restrict__ Eb,
    const float* __restrict__ Rb,
    float* __restrict__ out_h,
    float* __restrict__ out_e)
{
    extern __shared__ char smem[];
    int*    sidx = reinterpret_cast<int*>(smem + ESM_SIDX);
    __half* sBE  = reinterpret_cast<__half*>(smem + ESM_BE);
    __half* sBR  = reinterpret_cast<__half*>(smem + ESM_BR);
    __half* sA   = reinterpret_cast<__half*>(smem + ESM_A);   // AE then AK
    float*  projR = reinterpret_cast<float*>(smem + ESM_A);
    float*  projE = reinterpret_cast<float*>(smem + ESM_A + PROJ_HALF);
    unsigned int* sblk = reinterpret_cast<unsigned int*>(smem + ESM_SIDX + 512 - 4); // unused slot? keep separate:
    __shared__ unsigned int s_blk;

    const int tid = threadIdx.x;
    const int wid = tid >> 5;

    // ---- load weights into smem ONCE (cp.async) ----
    {
        uint32_t be = (uint32_t)__cvta_generic_to_shared(sBE);
        uint32_t br = (uint32_t)__cvta_generic_to_shared(sBR);
        for (int i = tid; i < KDIM * (CD / 8); i += 256) {
            int krow = i >> 4, q = i & 15;
            size_t goff = (size_t)krow * CD + q * 8;
            uint32_t soff = (uint32_t)(krow * BLD + q * 8) * 2;
            cp16(be + soff, &g_We[0][goff]);
            cp16(br + soff, &g_We[1][goff]);
        }
        cp_commit();
    }

    const int warp_m = wid & 1;    // edge half owner for staging
    const int warp_n = wid >> 1;   // 4 x 32 cols

    // first work item
    if (tid == 0) s_blk = atomicAdd(&g_blk, 1u);

    cp_wait_all();
    __syncthreads();
    unsigned int blk = s_blk;

    while (blk < NTILE) {
        const int r0 = blk * BM;

        // grab next work item early
        __syncthreads();               // prior epilogue reads of proj/A done
        if (tid == 0) s_blk = atomicAdd(&g_blk, 1u);

        if (tid < BM) {
            sidx[tid]      = src[r0 + tid];
            sidx[BM + tid] = dst[r0 + tid];
        }
        // ---- fill A (both matrices, full K), streaming loads ----
#pragma unroll
        for (int j = 0; j < 8; ++j) {
            int task = tid + 256 * j;          // 0..2047
            int mat  = task >> 10;             // 0=e, 1=kr
            int row  = (task >> 4) & 63;
            int seg  = task & 15;              // 8 floats
            const float* gsrc = (mat ? kr : e) + (size_t)(r0 + row) * KDIM + seg * 8;
            float4 v0 = __ldcs(reinterpret_cast<const float4*>(gsrc));
            float4 v1 = __ldcs(reinterpret_cast<const float4*>(gsrc) + 1);
            __half2 h0 = __halves2half2(__float2half_rn(v0.x), __float2half_rn(v0.y));
            __half2 h1 = __halves2half2(__float2half_rn(v0.z), __float2half_rn(v0.w));
            __half2 h2 = __halves2half2(__float2half_rn(v1.x), __float2half_rn(v1.y));
            __half2 h3 = __halves2half2(__float2half_rn(v1.z), __float2half_rn(v1.w));
            uint4 pk;
            pk.x = *reinterpret_cast<uint32_t*>(&h0);
            pk.y = *reinterpret_cast<uint32_t*>(&h1);
            pk.z = *reinterpret_cast<uint32_t*>(&h2);
            pk.w = *reinterpret_cast<uint32_t*>(&h3);
            *reinterpret_cast<uint4*>(sA + mat * (BM * AW) + row * AW + seg * 8) = pk;
        }
        __syncthreads();               // A + sidx visible

        // ---- MMA sweep: 8 k-steps, E and R ----
        wmma::fragment<wmma::accumulator, 16, 16, 16, float> accE[2][2], accR[2][2];
#pragma unroll
        for (int tm = 0; tm < 2; ++tm)
#pragma unroll
            for (int tn = 0; tn < 2; ++tn) {
                wmma::fill_fragment(accE[tm][tn], 0.0f);
                wmma::fill_fragment(accR[tm][tn], 0.0f);
            }
        __half* sAE = sA;
        __half* sAK = sA + BM * AW;
#pragma unroll
        for (int ks = 0; ks < 8; ++ks) {
            wmma::fragment<wmma::matrix_a, 16, 16, 16, __half, wmma::row_major> a[2];
            wmma::fragment<wmma::matrix_b, 16, 16, 16, __half, wmma::row_major> b[2];
#pragma unroll
            for (int tm = 0; tm < 2; ++tm)
                wmma::load_matrix_sync(a[tm], sAE + (warp_m * 32 + tm * 16) * AW + ks * 16, AW);
#pragma unroll
            for (int tn = 0; tn < 2; ++tn)
                wmma::load_matrix_sync(b[tn], sBE + ks * 16 * BLD + warp_n * 32 + tn * 16, BLD);
#pragma unroll
            for (int tm = 0; tm < 2; ++tm)
#pragma unroll
                for (int tn = 0; tn < 2; ++tn)
                    wmma::mma_sync(accE[tm][tn], a[tm], b[tn], accE[tm][tn]);
#pragma unroll
            for (int tm = 0; tm < 2; ++tm)
                wmma::load_matrix_sync(a[tm], sAK + (warp_m * 32 + tm * 16) * AW + ks * 16, AW);
#pragma unroll
            for (int tn = 0; tn < 2; ++tn)
                wmma::load_matrix_sync(b[tn], sBR + ks * 16 * BLD + warp_n * 32 + tn * 16, BLD);
#pragma unroll
            for (int tm = 0; tm < 2; ++tm)
#pragma unroll
                for (int tn = 0; tn < 2; ++tn)
                    wmma::mma_sync(accR[tm][tn], a[tm], b[tn], accR[tm][tn]);
        }

        // ---- two-pass epilogue: 32 edges per pass, 16 cols (1 head) per thread ----
#pragma unroll
        for (int p = 0; p < 2; ++p) {
            __syncthreads();           // p=0: MMAs done (A dead); p=1: pass-0 proj reads done
            if (warp_m == p) {
#pragma unroll
                for (int tm = 0; tm < 2; ++tm)
#pragma unroll
                    for (int tn = 0; tn < 2; ++tn) {
                        const int po = (tm * 16) * PLD + warp_n * 32 + tn * 16;
                        wmma::store_matrix_sync(projR + po, accR[tm][tn], PLD, wmma::mem_row_major);
                        wmma::store_matrix_sync(projE + po, accE[tm][tn], PLD, wmma::mem_row_major);
                    }
            }
            __syncthreads();

            const int el = tid & 31;           // edge within pass
            const int cg = tid >> 5;           // head index (16 cols)
            const int erow = p * 32 + el;
            const int cc = cg * 16;
            const int gedge = r0 + erow;
            const int sn = sidx[erow];
            const int dn = sidx[BM + erow];

            float vv[16];
            float s = 0.f;
            float* oe = out_e + (size_t)gedge * CD + cc;
#pragma unroll
            for (int q = 0; q < 4; ++q) {
                float4 rv  = *reinterpret_cast<const float4*>(projR + el * PLD + cc + q * 4);
                float4 rbv = *reinterpret_cast<const float4*>(Rb + cc + q * 4);
                float4 ev  = *reinterpret_cast<const float4*>(projE + el * PLD + cc + q * 4);
                float4 ebv = *reinterpret_cast<const float4*>(Eb + cc + q * 4);
                float4 kv  = *reinterpret_cast<const float4*>(g_Kh + (size_t)sn * CD + cc + q * 4);
                float4 qv  = *reinterpret_cast<const float4*>(g_Qh + (size_t)dn * CD + cc + q * 4);
                float4 v4  = *reinterpret_cast<const float4*>(g_Vh + (size_t)sn * CD + cc + q * 4);
                vv[q*4+0]=v4.x; vv[q*4+1]=v4.y; vv[q*4+2]=v4.z; vv[q*4+3]=v4.w;
                const float pr[4] = {rv.x + rbv.x, rv.y + rbv.y, rv.z + rbv.z, rv.w + rbv.w};
                const float pe[4] = {ev.x + ebv.x, ev.y + ebv.y, ev.z + ebv.z, ev.w + ebv.w};
                const float kk[4] = {kv.x, kv.y, kv.z, kv.w};
                const float qq[4] = {qv.x, qv.y, qv.z, qv.w};
                float sc[4];
#pragma unroll
                for (int j = 0; j < 4; ++j) {
                    float t = fmaf(kk[j] * qq[j], 0.25f, pr[j]) * pe[j];
                    sc[j] = t;
                    s += t;
                }
                __stcs(reinterpret_cast<float4*>(oe + q * 4),
                       make_float4(sc[0], sc[1], sc[2], sc[3]));
            }

            s = __expf(fminf(fmaxf(s, -5.0f), 5.0f));

            float* w = out_h + (size_t)dn * CD + cc;
#pragma unroll
            for (int q = 0; q < 4; ++q)
                red_add_v4(w + q * 4, vv[q*4+0]*s, vv[q*4+1]*s, vv[q*4+2]*s, vv[q*4+3]*s);
            atomicAdd(&g_z[(size_t)dn * NH + cg], s);
        }

        __syncthreads();               // s_blk stable for all threads
        blk = s_blk;
    }
}

// ================= node kernel: bf16 3-split (unchanged) =================
#define NSM_AH   0
#define NSM_AL   (NSM_AH + 64 * AFULL * 2)
#define NSM_BH   (NSM_AL + 64 * AFULL * 2)
#define NSM_BL   (NSM_BH + KDIM * BLD * 2)
#define NSM_TOTAL (NSM_BL + KDIM * BLD * 2)   // 104448

__global__ __launch_bounds__(256, 2) void node_proj_qkv_kernel(
    const float* __restrict__ h,
    const float* __restrict__ Qb, const float* __restrict__ Kb, const float* __restrict__ Vb,
    float* __restrict__ outQ, float* __restrict__ outK, float* __restrict__ outV)
{
    extern __shared__ char smem[];
    __nv_bfloat16* sAH = reinterpret_cast<__nv_bfloat16*>(smem + NSM_AH);
    __nv_bfloat16* sAL = reinterpret_cast<__nv_bfloat16*>(smem + NSM_AL);
    __nv_bfloat16* sBH = reinterpret_cast<__nv_bfloat16*>(smem + NSM_BH);
    __nv_bfloat16* sBL = reinterpret_cast<__nv_bfloat16*>(smem + NSM_BL);
    float*        proj = reinterpret_cast<float*>(smem + NSM_BH);   // alias B region

    const int tid = threadIdx.x;
    const int wid = tid >> 5;
    const int r0  = blockIdx.x * 64;

    for (int i = tid; i < 64 * 32; i += 256) {
        int row = i >> 5, kq = i & 31;
        float4 v = make_float4(0.f, 0.f, 0.f, 0.f);
        if (r0 + row < NN)
            v = reinterpret_cast<const float4*>(h + (size_t)(r0 + row) * KDIM)[kq];
        const float a[4] = {v.x, v.y, v.z, v.w};
        int off = row * AFULL + kq * 4;
#pragma unroll
        for (int j = 0; j < 4; ++j) {
            __nv_bfloat16 hh, ll;
            cvt_split_bf(a[j], hh, ll);
            sAH[off + j] = hh; sAL[off + j] = ll;
        }
    }

    const float* Bs[3] = {Qb, Kb, Vb};
    float* Os[3] = {outQ, outK, outV};

    const int warp_m = wid & 1;
    const int warp_n = wid >> 1;

    for (int m = 0; m < 3; ++m) {
        __syncthreads();
        for (int i = tid; i < KDIM * (CD / 8); i += 256) {
            int krow = i >> 4, q = i & 15;
            size_t goff = (size_t)krow * CD + q * 8;
            int soff = krow * BLD + q * 8;
            *reinterpret_cast<uint4*>(sBH + soff) = *reinterpret_cast<const uint4*>(&g_Wn_h[m][goff]);
            *reinterpret_cast<uint4*>(sBL + soff) = *reinterpret_cast<const uint4*>(&g_Wn_l[m][goff]);
        }
        __syncthreads();

        wmma::fragment<wmma::accumulator, 16, 16, 16, float> acc[2][2];
#pragma unroll
        for (int tm = 0; tm < 2; ++tm)
#pragma unroll
            for (int tn = 0; tn < 2; ++tn) wmma::fill_fragment(acc[tm][tn], 0.0f);

#pragma unroll
        for (int ks = 0; ks < KDIM / 16; ++ks) {
            wmma::fragment<wmma::matrix_a, 16, 16, 16, __nv_bfloat16, wmma::row_major> aH[2], aL[2];
            wmma::fragment<wmma::matrix_b, 16, 16, 16, __nv_bfloat16, wmma::row_major> bH[2], bL[2];
#pragma unroll
            for (int tm = 0; tm < 2; ++tm) {
                const int ar = warp_m * 32 + tm * 16;
                wmma::load_matrix_sync(aH[tm], sAH + ar * AFULL + ks * 16, AFULL);
                wmma::load_matrix_sync(aL[tm], sAL + ar * AFULL + ks * 16, AFULL);
            }
#pragma unroll
            for (int tn = 0; tn < 2; ++tn) {
                const int bc = warp_n * 32 + tn * 16;
                wmma::load_matrix_sync(bH[tn], sBH + ks * 16 * BLD + bc, BLD);
                wmma::load_matrix_sync(bL[tn], sBL + ks * 16 * BLD + bc, BLD);
            }
#pragma unroll
            for (int tm = 0; tm < 2; ++tm)
#pragma unroll
                for (int tn = 0; tn < 2; ++tn) {
                    wmma::mma_sync(acc[tm][tn], aH[tm], bH[tn], acc[tm][tn]);
                    wmma::mma_sync(acc[tm][tn], aH[tm], bL[tn], acc[tm][tn]);
                    wmma::mma_sync(acc[tm][tn], aL[tm], bH[tn], acc[tm][tn]);
                }
        }

        __syncthreads();
#pragma unroll
        for (int tm = 0; tm < 2; ++tm)
#pragma unroll
            for (int tn = 0; tn < 2; ++tn)
                wmma::store_matrix_sync(proj + (warp_m * 32 + tm * 16) * PLD + warp_n * 32 + tn * 16,
                                        acc[tm][tn], PLD, wmma::mem_row_major);
        __syncthreads();

        const int row = tid >> 2;
        const int cq  = (tid & 3) * 32;
        if (r0 + row < NN) {
            float* out = Os[m] + (size_t)(r0 + row) * CD + cq;
#pragma unroll
            for (int q = 0; q < 8; ++q) {
                float4 v  = *reinterpret_cast<const float4*>(proj + row * PLD + cq + q * 4);
                float4 bv = *reinterpret_cast<const float4*>(Bs[m] + cq + q * 4);
                reinterpret_cast<float4*>(out + q * 4)[0] =
                    make_float4(v.x + bv.x, v.y + bv.y, v.z + bv.z, v.w + bv.w);
            }
        }
    }
}

// ---------------- finalize ----------------
__global__ __launch_bounds__(256) void finalize_kernel(float* __restrict__ out_h)
{
    int i = blockIdx.x * 256 + threadIdx.x;
    const int total = NN * CD / 4;
    if (i >= total) return;
    int n  = i >> 5;
    int cg = i & 31;
    int head = cg >> 2;
    float z = g_z[(size_t)n * NH + head] + 1e-6f;
    float inv = 1.0f / z;
    float4 v = reinterpret_cast<float4*>(out_h)[i];
    v.x *= inv; v.y *= inv; v.z *= inv; v.w *= inv;
    reinterpret_cast<float4*>(out_h)[i] = v;
}

// ---------------- launch ----------------
extern "C" void kernel_launch(void* const* d_in, const int* in_sizes, int n_in,
                              void* d_out, int out_size)
{
    const float* h   = (const float*)d_in[0];
    const float* e   = (const float*)d_in[1];
    const float* kr  = (const float*)d_in[2];
    const int*   src = (const int*)  d_in[3];
    const int*   dst = (const int*)  d_in[4];
    const float* Qw  = (const float*)d_in[5];
    const float* Qb  = (const float*)d_in[6];
    const float* Kw  = (const float*)d_in[7];
    const float* Kb  = (const float*)d_in[8];
    const float* Vw  = (const float*)d_in[9];
    const float* Vb  = (const float*)d_in[10];
    const float* Ew  = (const float*)d_in[11];
    const float* Eb  = (const float*)d_in[12];
    const float* Rw  = (const float*)d_in[13];
    const float* Rb  = (const float*)d_in[14];

    float* out_h = (float*)d_out;
    float* out_e = (float*)d_out + (size_t)NN * CD;

    cudaFuncSetAttribute(node_proj_qkv_kernel, cudaFuncAttributeMaxDynamicSharedMemorySize, NSM_TOTAL);
    cudaFuncSetAttribute(edge_kernel,          cudaFuncAttributeMaxDynamicSharedMemorySize, ESM_TOTAL);

    cudaMemsetAsync(out_h, 0, (size_t)NN * CD * sizeof(float));
    void* zp = nullptr;
    cudaGetSymbolAddress(&zp, g_z);
    cudaMemsetAsync(zp, 0, (size_t)NN * NH * sizeof(float));
    void* bp = nullptr;
    cudaGetSymbolAddress(&bp, g_blk);
    cudaMemsetAsync(bp, 0, sizeof(unsigned int));

    void *qp, *kp, *vp;
    cudaGetSymbolAddress(&qp, g_Qh);
    cudaGetSymbolAddress(&kp, g_Kh);
    cudaGetSymbolAddress(&vp, g_Vh);

    convert_weights_kernel<<<(KDIM * CD + 255) / 256, 256>>>(Ew, Rw, Qw, Kw, Vw);

    const int nodeBlocks = (NN + 63) / 64;  // 782
    node_proj_qkv_kernel<<<nodeBlocks, 256, NSM_TOTAL>>>(
        h, Qb, Kb, Vb, (float*)qp, (float*)kp, (float*)vp);

    edge_kernel<<<296, 256, ESM_TOTAL>>>(e, kr, src, dst, Eb, Rb, out_h, out_e);

    const int finBlocks = (NN * CD / 4 + 255) / 256;
    finalize_kernel<<<finBlocks, 256>>>(out_h);
}

// round 13
// speedup vs baseline: 1.4185x; 1.4185x over previous
#include <cuda_runtime.h>
#include <cuda_bf16.h>
#include <cuda_fp16.h>
#include <mma.h>
#include <math.h>
#include <stdint.h>

using namespace nvcuda;

#define NN 50000
#define EE 800000
#define KDIM 128
#define CD 128
#define NH 8

#define BM 64        // edges per block (edge kernel)
#define CHK 32       // K chunk
#define KCH (KDIM / CHK)
#define ALD 40       // A smem leading dim (half)
#define AFULL 136    // A smem leading dim full-K (bf16, node)
#define BLD 136      // B smem leading dim (16-bit elems)
#define PLD 132      // proj smem leading dim (floats)

// ---------------- device scratch ----------------
__device__ float g_Qh[(size_t)NN * CD];
__device__ float g_Kh[(size_t)NN * CD];
__device__ float g_Vh[(size_t)NN * CD];
__device__ float g_s[(size_t)EE * NH];     // per-edge per-head exp weight
__device__ int   g_cnt[NN];
__device__ int   g_off[NN + 1];
__device__ int   g_cur[NN];
__device__ int2  g_epk[EE];                // (src, edge_id) sorted by dst
// edge weights: single fp16 (0=Ew 1=Rw)
__device__ __align__(16) __half g_We[2][KDIM * CD];
// node weights: bf16 hi/lo (0=Qw 1=Kw 2=Vw)
__device__ __align__(16) __nv_bfloat16 g_Wn_h[3][KDIM * CD];
__device__ __align__(16) __nv_bfloat16 g_Wn_l[3][KDIM * CD];

__device__ __forceinline__ void cvt_split_bf(float x, __nv_bfloat16& hi, __nv_bfloat16& lo) {
    hi = __float2bfloat16(x);
    lo = __float2bfloat16(x - __bfloat162float(hi));
}
__device__ __forceinline__ void cp16(uint32_t saddr, const void* gptr) {
    asm volatile("cp.async.cg.shared.global [%0], [%1], 16;"
                 :: "r"(saddr), "l"(gptr) : "memory");
}
__device__ __forceinline__ void cp_commit() {
    asm volatile("cp.async.commit_group;" ::: "memory");
}
__device__ __forceinline__ void cp_wait_all() {
    asm volatile("cp.async.wait_group 0;" ::: "memory");
}

// ---------------- weight conversion ----------------
__global__ __launch_bounds__(256) void convert_weights_kernel(
    const float* __restrict__ Ew, const float* __restrict__ Rw,
    const float* __restrict__ Qw, const float* __restrict__ Kw,
    const float* __restrict__ Vw)
{
    int i = blockIdx.x * 256 + threadIdx.x;
    if (i >= KDIM * CD) return;
    g_We[0][i] = __float2half_rn(Ew[i]);
    g_We[1][i] = __float2half_rn(Rw[i]);
    {
        __nv_bfloat16 h, l;
        cvt_split_bf(Qw[i], h, l); g_Wn_h[0][i] = h; g_Wn_l[0][i] = l;
        cvt_split_bf(Kw[i], h, l); g_Wn_h[1][i] = h; g_Wn_l[1][i] = l;
        cvt_split_bf(Vw[i], h, l); g_Wn_h[2][i] = h; g_Wn_l[2][i] = l;
    }
}

// ---------------- CSR build: histogram, scan, fill ----------------
__global__ __launch_bounds__(256) void hist_kernel(const int* __restrict__ dst)
{
    int e = blockIdx.x * 256 + threadIdx.x;
    if (e < EE) atomicAdd(&g_cnt[dst[e]], 1);
}

__global__ __launch_bounds__(1024) void scan_kernel()
{
    __shared__ int part[1024];
    const int t = threadIdx.x;
    const int CHUNK = (NN + 1023) / 1024;   // 49
    const int base = t * CHUNK;
    int sum = 0;
    for (int i = 0; i < CHUNK; ++i) {
        int idx = base + i;
        if (idx < NN) sum += g_cnt[idx];
    }
    part[t] = sum;
    __syncthreads();
    for (int d = 1; d < 1024; d <<= 1) {
        int v = (t >= d) ? part[t - d] : 0;
        __syncthreads();
        part[t] += v;
        __syncthreads();
    }
    int run = (t == 0) ? 0 : part[t - 1];
    for (int i = 0; i < CHUNK; ++i) {
        int idx = base + i;
        if (idx < NN) {
            g_off[idx] = run;
            g_cur[idx] = run;
            run += g_cnt[idx];
        }
    }
    if (t == 1023) g_off[NN] = run;
}

__global__ __launch_bounds__(256) void fill_kernel(
    const int* __restrict__ src, const int* __restrict__ dst)
{
    int e = blockIdx.x * 256 + threadIdx.x;
    if (e >= EE) return;
    int pos = atomicAdd(&g_cur[dst[e]], 1);
    g_epk[pos] = make_int2(src[e], e);
}

// ================= edge kernel (R11 base): fp16 A1xB1, writes e_out + g_s =================
#define ESM_SIDX  0
#define ESM_A     512
#define ABUF_SZ   (2 * BM * ALD * 2)
#define ESM_B     (ESM_A + 2 * ABUF_SZ)
#define SBT       (CHK * BLD * 2)
#define BBUF_SZ   (2 * SBT)
#define ESM_PROJE (ESM_B + 2 * BBUF_SZ)
#define ESM_TOTAL (ESM_PROJE + BM * PLD * 4)  // 89600

__global__ __launch_bounds__(256, 2) void edge_kernel(
    const float* __restrict__ e,
    const float* __restrict__ kr,
    const int*  __restrict__ src,
    const int*  __restrict__ dst,
    const float* __restrict__ Eb,
    const float* __restrict__ Rb,
    float* __restrict__ out_e)
{
    extern __shared__ char smem[];
    int*   sidx  = reinterpret_cast<int*>(smem + ESM_SIDX);
    float* projR = reinterpret_cast<float*>(smem + ESM_B);
    float* projE = reinterpret_cast<float*>(smem + ESM_PROJE);

    const int tid = threadIdx.x;
    const int wid = tid >> 5;
    const int r0  = blockIdx.x * BM;

    const int bkrow0 = tid >> 4;
    const int bq     = tid & 15;

    {
        uint32_t bdst = (uint32_t)__cvta_generic_to_shared(smem + ESM_B);
#pragma unroll
        for (int it = 0; it < 2; ++it) {
            int krow = bkrow0 + 16 * it;
            size_t goff = (size_t)krow * CD + bq * 8;
            uint32_t soff = (uint32_t)(krow * BLD + bq * 8) * 2;
            cp16(bdst + 0 * SBT + soff, &g_We[0][goff]);
            cp16(bdst + 1 * SBT + soff, &g_We[1][goff]);
        }
        cp_commit();
    }

    if (tid < BM) {
        sidx[tid]      = src[r0 + tid];
        sidx[BM + tid] = dst[r0 + tid];
    }

    const int warp_m = wid & 1;
    const int warp_n = wid >> 1;
    const int arow0 = tid >> 3;
    const int aq    = tid & 7;

    wmma::fragment<wmma::accumulator, 16, 16, 16, float> accE[2][2], accR[2][2];
#pragma unroll
    for (int tm = 0; tm < 2; ++tm)
#pragma unroll
        for (int tn = 0; tn < 2; ++tn) {
            wmma::fill_fragment(accE[tm][tn], 0.0f);
            wmma::fill_fragment(accR[tm][tn], 0.0f);
        }

    float4 pve[2], pvk[2];
#pragma unroll
    for (int it = 0; it < 2; ++it) {
        const int row = arow0 + 32 * it;
        pve[it] = *reinterpret_cast<const float4*>(e  + (size_t)(r0 + row) * KDIM + aq * 4);
        pvk[it] = *reinterpret_cast<const float4*>(kr + (size_t)(r0 + row) * KDIM + aq * 4);
    }

    for (int ch = 0; ch < KCH; ++ch) {
        const int ab = ch & 1;
        __half* sAE = reinterpret_cast<__half*>(smem + ESM_A + ab * ABUF_SZ);
        __half* sAK = sAE + BM * ALD;

#pragma unroll
        for (int it = 0; it < 2; ++it) {
            const int row = arow0 + 32 * it;
            const int off = row * ALD + aq * 4;
            __half2* pe2 = reinterpret_cast<__half2*>(sAE + off);
            __half2* pk2 = reinterpret_cast<__half2*>(sAK + off);
            pe2[0] = __halves2half2(__float2half_rn(pve[it].x), __float2half_rn(pve[it].y));
            pe2[1] = __halves2half2(__float2half_rn(pve[it].z), __float2half_rn(pve[it].w));
            pk2[0] = __halves2half2(__float2half_rn(pvk[it].x), __float2half_rn(pvk[it].y));
            pk2[1] = __halves2half2(__float2half_rn(pvk[it].z), __float2half_rn(pvk[it].w));
        }
        if (ch < KCH - 1) {
            const int gk = (ch + 1) * CHK + aq * 4;
#pragma unroll
            for (int it = 0; it < 2; ++it) {
                const int row = arow0 + 32 * it;
                pve[it] = *reinterpret_cast<const float4*>(e  + (size_t)(r0 + row) * KDIM + gk);
                pvk[it] = *reinterpret_cast<const float4*>(kr + (size_t)(r0 + row) * KDIM + gk);
            }
        }

        cp_wait_all();
        __syncthreads();

        if (ch < KCH - 1) {
            uint32_t bdst = (uint32_t)__cvta_generic_to_shared(
                smem + ESM_B + ((ch + 1) & 1) * BBUF_SZ);
#pragma unroll
            for (int it = 0; it < 2; ++it) {
                int krow = bkrow0 + 16 * it;
                size_t goff = (size_t)((ch + 1) * CHK + krow) * CD + bq * 8;
                uint32_t soff = (uint32_t)(krow * BLD + bq * 8) * 2;
                cp16(bdst + 0 * SBT + soff, &g_We[0][goff]);
                cp16(bdst + 1 * SBT + soff, &g_We[1][goff]);
            }
            cp_commit();
        }

        __half* sB  = reinterpret_cast<__half*>(smem + ESM_B + ab * BBUF_SZ);
        __half* sBE = sB;
        __half* sBR = sB + SBT / 2;

#pragma unroll
        for (int ks = 0; ks < 2; ++ks) {
            wmma::fragment<wmma::matrix_a, 16, 16, 16, __half, wmma::row_major> a[2];
            wmma::fragment<wmma::matrix_b, 16, 16, 16, __half, wmma::row_major> b[2];
#pragma unroll
            for (int tm = 0; tm < 2; ++tm)
                wmma::load_matrix_sync(a[tm], sAE + (warp_m * 32 + tm * 16) * ALD + ks * 16, ALD);
#pragma unroll
            for (int tn = 0; tn < 2; ++tn)
                wmma::load_matrix_sync(b[tn], sBE + ks * 16 * BLD + warp_n * 32 + tn * 16, BLD);
#pragma unroll
            for (int tm = 0; tm < 2; ++tm)
#pragma unroll
                for (int tn = 0; tn < 2; ++tn)
                    wmma::mma_sync(accE[tm][tn], a[tm], b[tn], accE[tm][tn]);
#pragma unroll
            for (int tm = 0; tm < 2; ++tm)
                wmma::load_matrix_sync(a[tm], sAK + (warp_m * 32 + tm * 16) * ALD + ks * 16, ALD);
#pragma unroll
            for (int tn = 0; tn < 2; ++tn)
                wmma::load_matrix_sync(b[tn], sBR + ks * 16 * BLD + warp_n * 32 + tn * 16, BLD);
#pragma unroll
            for (int tm = 0; tm < 2; ++tm)
#pragma unroll
                for (int tn = 0; tn < 2; ++tn)
                    wmma::mma_sync(accR[tm][tn], a[tm], b[tn], accR[tm][tn]);
        }
    }

    __syncthreads();
#pragma unroll
    for (int tm = 0; tm < 2; ++tm)
#pragma unroll
        for (int tn = 0; tn < 2; ++tn) {
            const int po = (warp_m * 32 + tm * 16) * PLD + warp_n * 32 + tn * 16;
            wmma::store_matrix_sync(projR + po, accR[tm][tn], PLD, wmma::mem_row_major);
            wmma::store_matrix_sync(projE + po, accE[tm][tn], PLD, wmma::mem_row_major);
        }
    __syncthreads();

    const int erow    = tid & 63;
    const int quarter = tid >> 6;
    const int cc      = quarter * 32;

    const int gedge = r0 + erow;
    const int sn = sidx[erow];
    const int dn = sidx[BM + erow];

    float s0 = 0.f, s1 = 0.f;
    float* oe = out_e + (size_t)gedge * CD + cc;
#pragma unroll
    for (int q = 0; q < 8; ++q) {
        float4 rv  = *reinterpret_cast<const float4*>(projR + erow * PLD + cc + q * 4);
        float4 rbv = *reinterpret_cast<const float4*>(Rb + cc + q * 4);
        float4 ev  = *reinterpret_cast<const float4*>(projE + erow * PLD + cc + q * 4);
        float4 ebv = *reinterpret_cast<const float4*>(Eb + cc + q * 4);
        float4 kv  = *reinterpret_cast<const float4*>(g_Kh + (size_t)sn * CD + cc + q * 4);
        float4 qv  = *reinterpret_cast<const float4*>(g_Qh + (size_t)dn * CD + cc + q * 4);
        const float pr[4] = {rv.x + rbv.x, rv.y + rbv.y, rv.z + rbv.z, rv.w + rbv.w};
        const float pe[4] = {ev.x + ebv.x, ev.y + ebv.y, ev.z + ebv.z, ev.w + ebv.w};
        const float kk[4] = {kv.x, kv.y, kv.z, kv.w};
        const float qq[4] = {qv.x, qv.y, qv.z, qv.w};
        float sc[4];
#pragma unroll
        for (int j = 0; j < 4; ++j) {
            float t = fmaf(kk[j] * qq[j], 0.25f, pr[j]) * pe[j];
            sc[j] = t;
            if (q < 4) s0 += t; else s1 += t;
        }
        __stcs(reinterpret_cast<float4*>(oe + q * 4), make_float4(sc[0], sc[1], sc[2], sc[3]));
    }

    s0 = __expf(fminf(fmaxf(s0, -5.0f), 5.0f));
    s1 = __expf(fminf(fmaxf(s1, -5.0f), 5.0f));

    // plain store of per-edge per-head weights (no atomics)
    *reinterpret_cast<float2*>(&g_s[(size_t)gedge * NH + quarter * 2]) = make_float2(s0, s1);
    (void)dn;
}

// ================= gather kernel: one warp per node, no atomics =================
__global__ __launch_bounds__(256) void gather_kernel(float* __restrict__ out_h)
{
    const int warp = (blockIdx.x * 256 + threadIdx.x) >> 5;
    const int lane = threadIdx.x & 31;
    if (warp >= NN) return;

    const int off0 = g_off[warp];
    const int off1 = g_off[warp + 1];
    const int head = lane >> 2;            // 4 lanes per head

    float4 acc = make_float4(0.f, 0.f, 0.f, 0.f);
    float zs = 0.f;

#pragma unroll 2
    for (int i = off0; i < off1; ++i) {
        int2 pk = g_epk[i];
        float s = g_s[(size_t)pk.y * NH + head];
        float4 v = *reinterpret_cast<const float4*>(g_Vh + (size_t)pk.x * CD + lane * 4);
        acc.x = fmaf(s, v.x, acc.x);
        acc.y = fmaf(s, v.y, acc.y);
        acc.z = fmaf(s, v.z, acc.z);
        acc.w = fmaf(s, v.w, acc.w);
        zs += s;
    }

    float inv = 1.0f / (zs + 1e-6f);
    acc.x *= inv; acc.y *= inv; acc.z *= inv; acc.w *= inv;
    *reinterpret_cast<float4*>(out_h + (size_t)warp * CD + lane * 4) = acc;
}

// ================= node kernel: bf16 3-split (unchanged) =================
#define NSM_AH   0
#define NSM_AL   (NSM_AH + 64 * AFULL * 2)
#define NSM_BH   (NSM_AL + 64 * AFULL * 2)
#define NSM_BL   (NSM_BH + KDIM * BLD * 2)
#define NSM_TOTAL (NSM_BL + KDIM * BLD * 2)   // 104448

__global__ __launch_bounds__(256, 2) void node_proj_qkv_kernel(
    const float* __restrict__ h,
    const float* __restrict__ Qb, const float* __restrict__ Kb, const float* __restrict__ Vb,
    float* __restrict__ outQ, float* __restrict__ outK, float* __restrict__ outV)
{
    extern __shared__ char smem[];
    __nv_bfloat16* sAH = reinterpret_cast<__nv_bfloat16*>(smem + NSM_AH);
    __nv_bfloat16* sAL = reinterpret_cast<__nv_bfloat16*>(smem + NSM_AL);
    __nv_bfloat16* sBH = reinterpret_cast<__nv_bfloat16*>(smem + NSM_BH);
    __nv_bfloat16* sBL = reinterpret_cast<__nv_bfloat16*>(smem + NSM_BL);
    float*        proj = reinterpret_cast<float*>(smem + NSM_BH);

    const int tid = threadIdx.x;
    const int wid = tid >> 5;
    const int r0  = blockIdx.x * 64;

    for (int i = tid; i < 64 * 32; i += 256) {
        int row = i >> 5, kq = i & 31;
        float4 v = make_float4(0.f, 0.f, 0.f, 0.f);
        if (r0 + row < NN)
            v = reinterpret_cast<const float4*>(h + (size_t)(r0 + row) * KDIM)[kq];
        const float a[4] = {v.x, v.y, v.z, v.w};
        int off = row * AFULL + kq * 4;
#pragma unroll
        for (int j = 0; j < 4; ++j) {
            __nv_bfloat16 hh, ll;
            cvt_split_bf(a[j], hh, ll);
            sAH[off + j] = hh; sAL[off + j] = ll;
        }
    }

    const float* Bs[3] = {Qb, Kb, Vb};
    float* Os[3] = {outQ, outK, outV};

    const int warp_m = wid & 1;
    const int warp_n = wid >> 1;

    for (int m = 0; m < 3; ++m) {
        __syncthreads();
        for (int i = tid; i < KDIM * (CD / 8); i += 256) {
            int krow = i >> 4, q = i & 15;
            size_t goff = (size_t)krow * CD + q * 8;
            int soff = krow * BLD + q * 8;
            *reinterpret_cast<uint4*>(sBH + soff) = *reinterpret_cast<const uint4*>(&g_Wn_h[m][goff]);
            *reinterpret_cast<uint4*>(sBL + soff) = *reinterpret_cast<const uint4*>(&g_Wn_l[m][goff]);
        }
        __syncthreads();

        wmma::fragment<wmma::accumulator, 16, 16, 16, float> acc[2][2];
#pragma unroll
        for (int tm = 0; tm < 2; ++tm)
#pragma unroll
            for (int tn = 0; tn < 2; ++tn) wmma::fill_fragment(acc[tm][tn], 0.0f);

#pragma unroll
        for (int ks = 0; ks < KDIM / 16; ++ks) {
            wmma::fragment<wmma::matrix_a, 16, 16, 16, __nv_bfloat16, wmma::row_major> aH[2], aL[2];
            wmma::fragment<wmma::matrix_b, 16, 16, 16, __nv_bfloat16, wmma::row_major> bH[2], bL[2];
#pragma unroll
            for (int tm = 0; tm < 2; ++tm) {
                const int ar = warp_m * 32 + tm * 16;
                wmma::load_matrix_sync(aH[tm], sAH + ar * AFULL + ks * 16, AFULL);
                wmma::load_matrix_sync(aL[tm], sAL + ar * AFULL + ks * 16, AFULL);
            }
#pragma unroll
            for (int tn = 0; tn < 2; ++tn) {
                const int bc = warp_n * 32 + tn * 16;
                wmma::load_matrix_sync(bH[tn], sBH + ks * 16 * BLD + bc, BLD);
                wmma::load_matrix_sync(bL[tn], sBL + ks * 16 * BLD + bc, BLD);
            }
#pragma unroll
            for (int tm = 0; tm < 2; ++tm)
#pragma unroll
                for (int tn = 0; tn < 2; ++tn) {
                    wmma::mma_sync(acc[tm][tn], aH[tm], bH[tn], acc[tm][tn]);
                    wmma::mma_sync(acc[tm][tn], aH[tm], bL[tn], acc[tm][tn]);
                    wmma::mma_sync(acc[tm][tn], aL[tm], bH[tn], acc[tm][tn]);
                }
        }

        __syncthreads();
#pragma unroll
        for (int tm = 0; tm < 2; ++tm)
#pragma unroll
            for (int tn = 0; tn < 2; ++tn)
                wmma::store_matrix_sync(proj + (warp_m * 32 + tm * 16) * PLD + warp_n * 32 + tn * 16,
                                        acc[tm][tn], PLD, wmma::mem_row_major);
        __syncthreads();

        const int row = tid >> 2;
        const int cq  = (tid & 3) * 32;
        if (r0 + row < NN) {
            float* out = Os[m] + (size_t)(r0 + row) * CD + cq;
#pragma unroll
            for (int q = 0; q < 8; ++q) {
                float4 v  = *reinterpret_cast<const float4*>(proj + row * PLD + cq + q * 4);
                float4 bv = *reinterpret_cast<const float4*>(Bs[m] + cq + q * 4);
                reinterpret_cast<float4*>(out + q * 4)[0] =
                    make_float4(v.x + bv.x, v.y + bv.y, v.z + bv.z, v.w + bv.w);
            }
        }
    }
}

// ---------------- launch ----------------
extern "C" void kernel_launch(void* const* d_in, const int* in_sizes, int n_in,
                              void* d_out, int out_size)
{
    const float* h   = (const float*)d_in[0];
    const float* e   = (const float*)d_in[1];
    const float* kr  = (const float*)d_in[2];
    const int*   src = (const int*)  d_in[3];
    const int*   dst = (const int*)  d_in[4];
    const float* Qw  = (const float*)d_in[5];
    const float* Qb  = (const float*)d_in[6];
    const float* Kw  = (const float*)d_in[7];
    const float* Kb  = (const float*)d_in[8];
    const float* Vw  = (const float*)d_in[9];
    const float* Vb  = (const float*)d_in[10];
    const float* Ew  = (const float*)d_in[11];
    const float* Eb  = (const float*)d_in[12];
    const float* Rw  = (const float*)d_in[13];
    const float* Rb  = (const float*)d_in[14];

    float* out_h = (float*)d_out;
    float* out_e = (float*)d_out + (size_t)NN * CD;

    cudaFuncSetAttribute(node_proj_qkv_kernel, cudaFuncAttributeMaxDynamicSharedMemorySize, NSM_TOTAL);
    cudaFuncSetAttribute(edge_kernel,          cudaFuncAttributeMaxDynamicSharedMemorySize, ESM_TOTAL);

    void* cp = nullptr;
    cudaGetSymbolAddress(&cp, g_cnt);
    cudaMemsetAsync(cp, 0, NN * sizeof(int));

    void *qp, *kp, *vp;
    cudaGetSymbolAddress(&qp, g_Qh);
    cudaGetSymbolAddress(&kp, g_Kh);
    cudaGetSymbolAddress(&vp, g_Vh);

    convert_weights_kernel<<<(KDIM * CD + 255) / 256, 256>>>(Ew, Rw, Qw, Kw, Vw);

    // CSR build (independent of projections)
    hist_kernel<<<(EE + 255) / 256, 256>>>(dst);
    scan_kernel<<<1, 1024>>>();
    fill_kernel<<<(EE + 255) / 256, 256>>>(src, dst);

    const int nodeBlocks = (NN + 63) / 64;  // 782
    node_proj_qkv_kernel<<<nodeBlocks, 256, NSM_TOTAL>>>(
        h, Qb, Kb, Vb, (float*)qp, (float*)kp, (float*)vp);

    edge_kernel<<<EE / BM, 256, ESM_TOTAL>>>(e, kr, src, dst, Eb, Rb, out_e);

    gather_kernel<<<(NN * 32 + 255) / 256, 256>>>(out_h);
}